// round 5
// baseline (speedup 1.0000x reference)
#include <cuda_runtime.h>
#include <math.h>

#define BATCH 128
#define SEQL  512
#define CH    321
#define PREDL 336
#define KWIN  25
#define NSEG  128          // SEQL / 4
#define HID   512
#define BC    (BATCH*CH)   // 41088
#define MMLP  (BC*4)       // 164352

// ---------------- static scratch (no allocation allowed) ----------------
__device__ float g_mean[BC];
__device__ float g_std [BC];
__device__ float g_xn  [(size_t)BC*SEQL];     //  84 MB   xn transposed [B*C, L]
__device__ float g_A   [(size_t)BC*1024];     // 168 MB   [trend | seasonal-out] per row
__device__ float g_xs  [(size_t)MMLP*NSEG];   //  84 MB   MLP activations (reused)
__device__ float g_h   [(size_t)MMLP*HID];    // 336 MB   MLP hidden (reused)
__device__ float g_w2  [1024*PREDL];          //  1.3 MB  [W_tr ; W_se]
__device__ float g_y   [(size_t)BC*PREDL];    //  55 MB   head output [B*C, PRED]

// ---------------- stage 1: per-(b,c) mean / std over L ----------------
__global__ void stats_kernel(const float* __restrict__ x) {
    int c = blockIdx.x * 128 + threadIdx.x;
    int b = blockIdx.y;
    if (c >= CH) return;
    const float* p = x + (size_t)b * SEQL * CH + c;
    float s = 0.f, s2 = 0.f;
    #pragma unroll 4
    for (int l = 0; l < SEQL; ++l) {
        float v = p[(size_t)l * CH];
        s  += v;
        s2 += v * v;
    }
    float m   = s  * (1.0f / SEQL);
    float var = s2 * (1.0f / SEQL) - m * m;
    var = fmaxf(var, 0.0f);
    g_mean[b*CH + c] = m;
    g_std [b*CH + c] = sqrtf(var + 1e-5f);
}

// ---------------- stage 2: normalize + transpose to [B*C, L] ----------------
__global__ void norm_transpose_kernel(const float* __restrict__ x,
                                      const float* __restrict__ rw,
                                      const float* __restrict__ rb) {
    __shared__ float sm[32][33];
    int b  = blockIdx.z;
    int l0 = blockIdx.x * 32, c0 = blockIdx.y * 32;
    int tx = threadIdx.x, ty = threadIdx.y;
    int c = c0 + tx, l = l0 + ty;           // L is a multiple of 32
    if (c < CH) sm[ty][tx] = x[((size_t)b * SEQL + l) * CH + c];
    __syncthreads();
    int cw = c0 + ty, lw = l0 + tx;
    if (cw < CH) {
        float m  = g_mean[b*CH + cw];
        float sd = g_std [b*CH + cw];
        float v  = (sm[tx][ty] - m) / sd * rw[cw] + rb[cw];
        g_xn[((size_t)(b*CH + cw)) * SEQL + lw] = v;
    }
}

// ---------------- stage 3: moving-avg decomp + interleave seasonal ----------------
__global__ void decomp_kernel() {
    __shared__ float sm[SEQL];
    int row = blockIdx.x;          // b*CH + c
    int l   = threadIdx.x;
    float v = g_xn[(size_t)row * SEQL + l];
    sm[l] = v;
    __syncthreads();
    float s = 0.f;
    #pragma unroll
    for (int d = -12; d <= 12; ++d) {
        int j = l + d;
        j = j < 0 ? 0 : (j > SEQL - 1 ? SEQL - 1 : j);
        s += sm[j];
    }
    float trend = s * (1.0f / KWIN);
    float sea   = v - trend;
    g_A[(size_t)row * 1024 + l] = trend;                       // head-A cols 0..511
    g_xs[((size_t)row * 4 + (l & 3)) * NSEG + (l >> 2)] = sea; // xs[b,c,s,n]
}

// ---------------- tiled fp32 GEMM: C = act(A@B + bias [+bias2]) ----------------
#define BM 128
#define BN 128
#define BKG 8

template<int GELU, int INTERLEAVE>
__global__ __launch_bounds__(256)
void sgemm_kernel(const float* __restrict__ A, const float* __restrict__ B,
                  const float* __restrict__ bias, const float* __restrict__ bias2,
                  float* __restrict__ Cout, int M, int Kd, int Nd) {
    __shared__ float As[2][BKG][BM];
    __shared__ float Bs[2][BKG][BN];
    const int tid = threadIdx.x;
    const int m0 = blockIdx.y * BM;
    const int n0 = blockIdx.x * BN;
    const int a_row = tid >> 1, a_col = (tid & 1) * 4;
    const int b_row = tid >> 5, b_col = (tid & 31) * 4;
    const float* Ap = A + (size_t)(m0 + a_row) * Kd + a_col;
    const int tm = (tid >> 4) * 8, tn = (tid & 15) * 8;

    float acc[8][8];
    #pragma unroll
    for (int i = 0; i < 8; ++i)
        #pragma unroll
        for (int j = 0; j < 8; ++j) acc[i][j] = 0.f;

    auto fetchB = [&](int k0, float4& bv) {
        int bn = n0 + b_col;
        const float* Bp = B + (size_t)(k0 + b_row) * Nd + bn;
        if (bn + 3 < Nd) {
            bv = *reinterpret_cast<const float4*>(Bp);
        } else {
            bv.x = (bn + 0 < Nd) ? Bp[0] : 0.f;
            bv.y = (bn + 1 < Nd) ? Bp[1] : 0.f;
            bv.z = (bn + 2 < Nd) ? Bp[2] : 0.f;
            bv.w = 0.f;
        }
    };
    auto stage = [&](int buf, float4 av, float4 bv) {
        As[buf][a_col + 0][a_row] = av.x;
        As[buf][a_col + 1][a_row] = av.y;
        As[buf][a_col + 2][a_row] = av.z;
        As[buf][a_col + 3][a_row] = av.w;
        *reinterpret_cast<float4*>(&Bs[buf][b_row][b_col]) = bv;
    };

    // prologue: fill buffer 0
    {
        float4 av = *reinterpret_cast<const float4*>(Ap);
        float4 bv; fetchB(0, bv);
        stage(0, av, bv);
    }
    __syncthreads();

    const int nk = Kd / BKG;
    for (int t = 0; t < nk; ++t) {
        const int cur = t & 1;
        float4 av, bv;
        if (t + 1 < nk) {                         // prefetch into registers
            av = *reinterpret_cast<const float4*>(Ap + (t + 1) * BKG);
            fetchB((t + 1) * BKG, bv);
        }
        #pragma unroll
        for (int kk = 0; kk < BKG; ++kk) {
            float4 a0 = *reinterpret_cast<const float4*>(&As[cur][kk][tm]);
            float4 a1 = *reinterpret_cast<const float4*>(&As[cur][kk][tm + 4]);
            float4 b0 = *reinterpret_cast<const float4*>(&Bs[cur][kk][tn]);
            float4 b1 = *reinterpret_cast<const float4*>(&Bs[cur][kk][tn + 4]);
            float ra[8] = {a0.x, a0.y, a0.z, a0.w, a1.x, a1.y, a1.z, a1.w};
            float rb[8] = {b0.x, b0.y, b0.z, b0.w, b1.x, b1.y, b1.z, b1.w};
            #pragma unroll
            for (int i = 0; i < 8; ++i)
                #pragma unroll
                for (int j = 0; j < 8; ++j)
                    acc[i][j] = fmaf(ra[i], rb[j], acc[i][j]);
        }
        if (t + 1 < nk) stage(cur ^ 1, av, bv);
        __syncthreads();
    }

    // epilogue
    #pragma unroll
    for (int i = 0; i < 8; ++i) {
        int row = m0 + tm + i;                    // M always multiple of 128 here
        #pragma unroll
        for (int j = 0; j < 8; ++j) {
            int col = n0 + tn + j;
            if (col < Nd) {
                float v = acc[i][j] + bias[col];
                if (bias2) v += bias2[col];
                if (GELU)  v = 0.5f * v * (1.0f + erff(v * 0.70710678118654752f));
                if (INTERLEAVE)
                    // sea[b,c, l=n*4+s] into head-A cols 512..1023
                    Cout[((size_t)(row >> 2)) * 1024 + 512 + (size_t)col * 4 + (row & 3)] = v;
                else
                    Cout[(size_t)row * Nd + col] = v;
            }
        }
    }
}

// ---------------- stage: concat [W_tr ; W_se] into [1024, PRED] ----------------
__global__ void concat_w_kernel(const float* __restrict__ Wtr,
                                const float* __restrict__ Wse) {
    int idx = blockIdx.x * 256 + threadIdx.x;
    if (idx >= 1024 * PREDL) return;
    int k = idx / PREDL, p = idx - k * PREDL;
    g_w2[idx] = (k < 512) ? Wtr[(size_t)k * PREDL + p]
                          : Wse[(size_t)(k - 512) * PREDL + p];
}

// ---------------- final: denorm + transpose to [B, PRED, C] ----------------
__global__ void final_kernel(const float* __restrict__ rw,
                             const float* __restrict__ rb,
                             float* __restrict__ out) {
    __shared__ float sm[32][33];
    int b  = blockIdx.z;
    int p0 = blockIdx.x * 32, c0 = blockIdx.y * 32;
    int tx = threadIdx.x, ty = threadIdx.y;
    int p = p0 + tx, c = c0 + ty;
    if (p < PREDL && c < CH)
        sm[ty][tx] = g_y[((size_t)(b*CH + c)) * PREDL + p];
    __syncthreads();
    int cw = c0 + tx, pw = p0 + ty;
    if (cw < CH && pw < PREDL) {
        float v = sm[tx][ty];
        v = (v - rb[cw]) / (rw[cw] + 1e-10f);
        v = v * g_std[b*CH + cw] + g_mean[b*CH + cw];
        out[((size_t)b * PREDL + pw) * CH + cw] = v;
    }
}

// ---------------- launch ----------------
extern "C" void kernel_launch(void* const* d_in, const int* in_sizes, int n_in,
                              void* d_out, int out_size) {
    const float* x   = (const float*)d_in[0];
    const float* rw  = (const float*)d_in[1];
    const float* rb  = (const float*)d_in[2];
    const float* W11 = (const float*)d_in[3];
    const float* b11 = (const float*)d_in[4];
    const float* W12 = (const float*)d_in[5];
    const float* b12 = (const float*)d_in[6];
    const float* W21 = (const float*)d_in[7];
    const float* b21 = (const float*)d_in[8];
    const float* W22 = (const float*)d_in[9];
    const float* b22 = (const float*)d_in[10];
    const float* Wtr = (const float*)d_in[11];
    const float* btr = (const float*)d_in[12];
    const float* Wse = (const float*)d_in[13];
    const float* bse = (const float*)d_in[14];
    float* out = (float*)d_out;
    (void)in_sizes; (void)n_in; (void)out_size;

    float *p_A, *p_xs, *p_h, *p_w2, *p_y;
    cudaGetSymbolAddress((void**)&p_A,  g_A);
    cudaGetSymbolAddress((void**)&p_xs, g_xs);
    cudaGetSymbolAddress((void**)&p_h,  g_h);
    cudaGetSymbolAddress((void**)&p_w2, g_w2);
    cudaGetSymbolAddress((void**)&p_y,  g_y);

    // 1) RevIN statistics
    stats_kernel<<<dim3((CH + 127) / 128, BATCH), 128>>>(x);
    // 2) normalize + transpose to [B*C, L]
    norm_transpose_kernel<<<dim3(SEQL / 32, (CH + 31) / 32, BATCH), dim3(32, 32)>>>(x, rw, rb);
    // 3) moving-average decomposition (trend -> head A; seasonal -> interleaved xs)
    decomp_kernel<<<BC, SEQL>>>();
    // 4) seasonal MLP: N->H (gelu) -> N -> H (gelu) -> N (interleaved store into head A)
    sgemm_kernel<1, 0><<<dim3(HID / BN,  MMLP / BM), 256>>>(p_xs, W11, b11, nullptr, p_h,  MMLP, NSEG, HID);
    sgemm_kernel<0, 0><<<dim3(1,         MMLP / BM), 256>>>(p_h,  W12, b12, nullptr, p_xs, MMLP, HID,  NSEG);
    sgemm_kernel<1, 0><<<dim3(HID / BN,  MMLP / BM), 256>>>(p_xs, W21, b21, nullptr, p_h,  MMLP, NSEG, HID);
    sgemm_kernel<0, 1><<<dim3(1,         MMLP / BM), 256>>>(p_h,  W22, b22, nullptr, p_A,  MMLP, HID,  NSEG);
    // 5) fused heads: [trend|sea] @ [W_tr;W_se] + b_tr + b_se
    concat_w_kernel<<<(1024 * PREDL + 255) / 256, 256>>>(Wtr, Wse);
    sgemm_kernel<0, 0><<<dim3((PREDL + BN - 1) / BN, BC / BM), 256>>>(p_A, p_w2, btr, bse, p_y, BC, 1024, PREDL);
    // 6) denorm + transpose to [B, PRED, C]
    final_kernel<<<dim3((PREDL + 31) / 32, (CH + 31) / 32, BATCH), dim3(32, 32)>>>(rw, rb, out);
}

// round 6
// speedup vs baseline: 1.4204x; 1.4204x over previous
#include <cuda_runtime.h>
#include <math.h>
#include <stdint.h>

#define BATCH 128
#define SEQL  512
#define CH    321
#define PREDL 336
#define KWIN  25
#define NSEG  128          // SEQL / 4
#define HID   512
#define BC    (BATCH*CH)   // 41088
#define MMLP  (BC*4)       // 164352

// ---------------- static scratch (no allocation allowed) ----------------
__device__ float g_mean[BC];
__device__ float g_std [BC];
__device__ float g_xn  [(size_t)BC*SEQL];     //  84 MB   xn transposed [B*C, L]
__device__ float g_A   [(size_t)BC*1024];     // 168 MB   [trend | seasonal-out] per row
__device__ float g_xs  [(size_t)MMLP*NSEG];   //  84 MB   MLP activations (reused)
__device__ float g_h   [(size_t)MMLP*HID];    // 336 MB   MLP hidden (reused)
__device__ float g_w2  [1024*PREDL];          //  1.3 MB  [W_tr ; W_se]
__device__ float g_y   [(size_t)BC*PREDL];    //  55 MB   head output [B*C, PRED]

// ---------------- stage 1: per-(b,c) mean / std over L ----------------
__global__ void stats_kernel(const float* __restrict__ x) {
    int c = blockIdx.x * 128 + threadIdx.x;
    int b = blockIdx.y;
    if (c >= CH) return;
    const float* p = x + (size_t)b * SEQL * CH + c;
    float s = 0.f, s2 = 0.f;
    #pragma unroll 4
    for (int l = 0; l < SEQL; ++l) {
        float v = p[(size_t)l * CH];
        s  += v;
        s2 += v * v;
    }
    float m   = s  * (1.0f / SEQL);
    float var = s2 * (1.0f / SEQL) - m * m;
    var = fmaxf(var, 0.0f);
    g_mean[b*CH + c] = m;
    g_std [b*CH + c] = sqrtf(var + 1e-5f);
}

// ---------------- stage 2: normalize + transpose to [B*C, L] ----------------
__global__ void norm_transpose_kernel(const float* __restrict__ x,
                                      const float* __restrict__ rw,
                                      const float* __restrict__ rb) {
    __shared__ float sm[32][33];
    int b  = blockIdx.z;
    int l0 = blockIdx.x * 32, c0 = blockIdx.y * 32;
    int tx = threadIdx.x, ty = threadIdx.y;
    int c = c0 + tx, l = l0 + ty;
    if (c < CH) sm[ty][tx] = x[((size_t)b * SEQL + l) * CH + c];
    __syncthreads();
    int cw = c0 + ty, lw = l0 + tx;
    if (cw < CH) {
        float m  = g_mean[b*CH + cw];
        float sd = g_std [b*CH + cw];
        float v  = (sm[tx][ty] - m) / sd * rw[cw] + rb[cw];
        g_xn[((size_t)(b*CH + cw)) * SEQL + lw] = v;
    }
}

// ---------------- stage 3: moving-avg decomp + interleave seasonal ----------------
__global__ void decomp_kernel() {
    __shared__ float sm[SEQL];
    int row = blockIdx.x;          // b*CH + c
    int l   = threadIdx.x;
    float v = g_xn[(size_t)row * SEQL + l];
    sm[l] = v;
    __syncthreads();
    float s = 0.f;
    #pragma unroll
    for (int d = -12; d <= 12; ++d) {
        int j = l + d;
        j = j < 0 ? 0 : (j > SEQL - 1 ? SEQL - 1 : j);
        s += sm[j];
    }
    float trend = s * (1.0f / KWIN);
    float sea   = v - trend;
    g_A[(size_t)row * 1024 + l] = trend;                       // head-A cols 0..511
    g_xs[((size_t)row * 4 + (l & 3)) * NSEG + (l >> 2)] = sea; // xs[b,c,s,n]
}

// ======================= tf32x3 tensor-core GEMM =======================
// C = act(A[M,K] @ B[K,N] + bias [+bias2]); tiles 128x128x16, 256 threads,
// 8 warps each owning a 64x32 warp tile of m16n8k8 tf32 MMA fragments.

__device__ __forceinline__ uint32_t f2tf(float x) {
    uint32_t r;
    asm("cvt.rna.tf32.f32 %0, %1;" : "=r"(r) : "f"(x));
    return r;
}

__device__ __forceinline__ void mma8(float4& d, uint32_t a0, uint32_t a1,
                                     uint32_t a2, uint32_t a3,
                                     uint32_t b0, uint32_t b1) {
    asm volatile(
        "mma.sync.aligned.m16n8k8.row.col.f32.tf32.tf32.f32 "
        "{%0,%1,%2,%3},{%4,%5,%6,%7},{%8,%9},{%0,%1,%2,%3};"
        : "+f"(d.x), "+f"(d.y), "+f"(d.z), "+f"(d.w)
        : "r"(a0), "r"(a1), "r"(a2), "r"(a3), "r"(b0), "r"(b1));
}

__device__ __forceinline__ void cp16(uint32_t dst, const void* src, int bytes) {
    asm volatile("cp.async.cg.shared.global [%0], [%1], 16, %2;\n"
                 :: "r"(dst), "l"(src), "r"(bytes));
}

#define BKT 16
#define APAD 20    // A smem row stride (words): 16B-aligned rows, conflict-free frags
#define BPAD 136   // B smem row stride (words): (tig*136+gid)%32 bijective

template<int GELU, int INTERLEAVE>
__global__ __launch_bounds__(256)
void tgemm_kernel(const float* __restrict__ A, const float* __restrict__ B,
                  const float* __restrict__ bias, const float* __restrict__ bias2,
                  float* __restrict__ Cout, int M, int Kd, int Nd) {
    __shared__ float As[2][128][APAD];
    __shared__ float Bs[2][BKT][BPAD];

    const int tid  = threadIdx.x;
    const int lane = tid & 31, wid = tid >> 5;
    const int gid  = lane >> 2, tig = lane & 3;
    const int wm   = (wid & 1) * 64;
    const int wn   = (wid >> 1) * 32;
    const int m0   = blockIdx.y * 128;
    const int n0   = blockIdx.x * 128;

    const uint32_t As_base = (uint32_t)__cvta_generic_to_shared(&As[0][0][0]);
    const uint32_t Bs_base = (uint32_t)__cvta_generic_to_shared(&Bs[0][0][0]);

    float4 acc[4][4];
    #pragma unroll
    for (int i = 0; i < 4; ++i)
        #pragma unroll
        for (int j = 0; j < 4; ++j) acc[i][j] = make_float4(0.f, 0.f, 0.f, 0.f);

    auto fill = [&](int t, int buf) {
        const int k0 = t * BKT;
        #pragma unroll
        for (int i = 0; i < 2; ++i) {
            int task = tid + 256 * i;
            // A: 128 rows x 4 chunks of 16B
            int ar = task >> 2, ac = (task & 3) * 4;
            cp16(As_base + (uint32_t)(((buf * 128 + ar) * APAD + ac) * 4),
                 A + (size_t)(m0 + ar) * Kd + k0 + ac, 16);
            // B: 16 rows x 32 chunks of 16B (zero-fill past Nd)
            int br = task >> 5, bcc = (task & 31) * 4;
            int bn = n0 + bcc;
            int bytes = (Nd - bn) * 4;
            bytes = bytes < 0 ? 0 : (bytes > 16 ? 16 : bytes);
            cp16(Bs_base + (uint32_t)(((buf * BKT + br) * BPAD + bcc) * 4),
                 B + (size_t)(k0 + br) * Nd + (bytes > 0 ? bn : 0), bytes);
        }
    };

    fill(0, 0);
    asm volatile("cp.async.commit_group;");
    asm volatile("cp.async.wait_group 0;");
    __syncthreads();

    const int nk = Kd / BKT;
    for (int t = 0; t < nk; ++t) {
        const int buf = t & 1;
        if (t + 1 < nk) {
            fill(t + 1, buf ^ 1);
            asm volatile("cp.async.commit_group;");
        }
        #pragma unroll
        for (int kk = 0; kk < BKT; kk += 8) {
            // B fragments (hi/lo)
            uint32_t bh[4][2], bl[4][2];
            #pragma unroll
            for (int nt = 0; nt < 4; ++nt) {
                float b0 = Bs[buf][kk + tig    ][wn + nt * 8 + gid];
                float b1 = Bs[buf][kk + tig + 4][wn + nt * 8 + gid];
                bh[nt][0] = f2tf(b0);
                bh[nt][1] = f2tf(b1);
                bl[nt][0] = f2tf(b0 - __uint_as_float(bh[nt][0]));
                bl[nt][1] = f2tf(b1 - __uint_as_float(bh[nt][1]));
            }
            #pragma unroll
            for (int mt = 0; mt < 4; ++mt) {
                float a0 = As[buf][wm + mt * 16 + gid    ][kk + tig    ];
                float a1 = As[buf][wm + mt * 16 + gid + 8][kk + tig    ];
                float a2 = As[buf][wm + mt * 16 + gid    ][kk + tig + 4];
                float a3 = As[buf][wm + mt * 16 + gid + 8][kk + tig + 4];
                uint32_t ah0 = f2tf(a0), ah1 = f2tf(a1), ah2 = f2tf(a2), ah3 = f2tf(a3);
                uint32_t al0 = f2tf(a0 - __uint_as_float(ah0));
                uint32_t al1 = f2tf(a1 - __uint_as_float(ah1));
                uint32_t al2 = f2tf(a2 - __uint_as_float(ah2));
                uint32_t al3 = f2tf(a3 - __uint_as_float(ah3));
                #pragma unroll
                for (int nt = 0; nt < 4; ++nt)
                    mma8(acc[mt][nt], ah0, ah1, ah2, ah3, bh[nt][0], bh[nt][1]);
                #pragma unroll
                for (int nt = 0; nt < 4; ++nt)
                    mma8(acc[mt][nt], ah0, ah1, ah2, ah3, bl[nt][0], bl[nt][1]);
                #pragma unroll
                for (int nt = 0; nt < 4; ++nt)
                    mma8(acc[mt][nt], al0, al1, al2, al3, bh[nt][0], bh[nt][1]);
            }
        }
        if (t + 1 < nk) asm volatile("cp.async.wait_group 0;");
        __syncthreads();
    }

    // epilogue
    auto emit = [&](int row, int col, float v) {
        if (col >= Nd) return;
        v += bias[col];
        if (bias2) v += bias2[col];
        if (GELU)  v = 0.5f * v * (1.0f + erff(v * 0.70710678118654752f));
        if (INTERLEAVE)
            Cout[((size_t)(row >> 2)) * 1024 + 512 + (size_t)col * 4 + (row & 3)] = v;
        else
            Cout[(size_t)row * Nd + col] = v;
    };
    #pragma unroll
    for (int mt = 0; mt < 4; ++mt) {
        int r0 = m0 + wm + mt * 16 + gid;
        #pragma unroll
        for (int nt = 0; nt < 4; ++nt) {
            int c0 = n0 + wn + nt * 8 + 2 * tig;
            float4 c = acc[mt][nt];
            emit(r0,     c0,     c.x);
            emit(r0,     c0 + 1, c.y);
            emit(r0 + 8, c0,     c.z);
            emit(r0 + 8, c0 + 1, c.w);
        }
    }
}

// ---------------- stage: concat [W_tr ; W_se] into [1024, PRED] ----------------
__global__ void concat_w_kernel(const float* __restrict__ Wtr,
                                const float* __restrict__ Wse) {
    int idx = blockIdx.x * 256 + threadIdx.x;
    if (idx >= 1024 * PREDL) return;
    int k = idx / PREDL, p = idx - k * PREDL;
    g_w2[idx] = (k < 512) ? Wtr[(size_t)k * PREDL + p]
                          : Wse[(size_t)(k - 512) * PREDL + p];
}

// ---------------- final: denorm + transpose to [B, PRED, C] ----------------
__global__ void final_kernel(const float* __restrict__ rw,
                             const float* __restrict__ rb,
                             float* __restrict__ out) {
    __shared__ float sm[32][33];
    int b  = blockIdx.z;
    int p0 = blockIdx.x * 32, c0 = blockIdx.y * 32;
    int tx = threadIdx.x, ty = threadIdx.y;
    int p = p0 + tx, c = c0 + ty;
    if (p < PREDL && c < CH)
        sm[ty][tx] = g_y[((size_t)(b*CH + c)) * PREDL + p];
    __syncthreads();
    int cw = c0 + tx, pw = p0 + ty;
    if (cw < CH && pw < PREDL) {
        float v = sm[tx][ty];
        v = (v - rb[cw]) / (rw[cw] + 1e-10f);
        v = v * g_std[b*CH + cw] + g_mean[b*CH + cw];
        out[((size_t)b * PREDL + pw) * CH + cw] = v;
    }
}

// ---------------- launch ----------------
extern "C" void kernel_launch(void* const* d_in, const int* in_sizes, int n_in,
                              void* d_out, int out_size) {
    const float* x   = (const float*)d_in[0];
    const float* rw  = (const float*)d_in[1];
    const float* rb  = (const float*)d_in[2];
    const float* W11 = (const float*)d_in[3];
    const float* b11 = (const float*)d_in[4];
    const float* W12 = (const float*)d_in[5];
    const float* b12 = (const float*)d_in[6];
    const float* W21 = (const float*)d_in[7];
    const float* b21 = (const float*)d_in[8];
    const float* W22 = (const float*)d_in[9];
    const float* b22 = (const float*)d_in[10];
    const float* Wtr = (const float*)d_in[11];
    const float* btr = (const float*)d_in[12];
    const float* Wse = (const float*)d_in[13];
    const float* bse = (const float*)d_in[14];
    float* out = (float*)d_out;
    (void)in_sizes; (void)n_in; (void)out_size;

    float *p_A, *p_xs, *p_h, *p_w2, *p_y;
    cudaGetSymbolAddress((void**)&p_A,  g_A);
    cudaGetSymbolAddress((void**)&p_xs, g_xs);
    cudaGetSymbolAddress((void**)&p_h,  g_h);
    cudaGetSymbolAddress((void**)&p_w2, g_w2);
    cudaGetSymbolAddress((void**)&p_y,  g_y);

    // 1) RevIN statistics
    stats_kernel<<<dim3((CH + 127) / 128, BATCH), 128>>>(x);
    // 2) normalize + transpose to [B*C, L]
    norm_transpose_kernel<<<dim3(SEQL / 32, (CH + 31) / 32, BATCH), dim3(32, 32)>>>(x, rw, rb);
    // 3) moving-average decomposition
    decomp_kernel<<<BC, SEQL>>>();
    // 4) seasonal MLP (tf32x3 tensor-core GEMMs)
    tgemm_kernel<1, 0><<<dim3(HID / 128, MMLP / 128), 256>>>(p_xs, W11, b11, nullptr, p_h,  MMLP, NSEG, HID);
    tgemm_kernel<0, 0><<<dim3(1,         MMLP / 128), 256>>>(p_h,  W12, b12, nullptr, p_xs, MMLP, HID,  NSEG);
    tgemm_kernel<1, 0><<<dim3(HID / 128, MMLP / 128), 256>>>(p_xs, W21, b21, nullptr, p_h,  MMLP, NSEG, HID);
    tgemm_kernel<0, 1><<<dim3(1,         MMLP / 128), 256>>>(p_h,  W22, b22, nullptr, p_A,  MMLP, HID,  NSEG);
    // 5) fused heads
    concat_w_kernel<<<(1024 * PREDL + 255) / 256, 256>>>(Wtr, Wse);
    tgemm_kernel<0, 0><<<dim3((PREDL + 127) / 128, BC / 128), 256>>>(p_A, p_w2, btr, bse, p_y, BC, 1024, PREDL);
    // 6) denorm + transpose to [B, PRED, C]
    final_kernel<<<dim3((PREDL + 31) / 32, (CH + 31) / 32, BATCH), dim3(32, 32)>>>(rw, rb, out);
}